// round 9
// baseline (speedup 1.0000x reference)
#include <cuda_runtime.h>
#include <cuda_fp16.h>
#include <cstdint>
#include <math.h>

#define NBUOY 16384
#define HID   1024
#define TH    3072
#define INP   1088
#define NEMB  100

// Tiles
#define BM  128
#define BNG 32      // per-gate N tile (3 gates -> 96 output cols per CTA)
#define BK  128     // K per chunk (two 64-wide swizzled halves)

// Stage: A 32KB (2 x 16KB halves) + 3 B gates x 8KB (2 x 4KB halves) = 56KB
#define STAGE_BYTES 57344
#define SMEM_BYTES  (2 * STAGE_BYTES)   // 112KB -> 2 CTAs/SM

// ---------------------------------------------------------------------------
// Scratch (device globals)
// ---------------------------------------------------------------------------
__device__ __half g_wih_h[TH * INP];
__device__ __half g_whh_h[TH * HID];
__device__ __half g_obs_h[NBUOY * 512];
__device__ __half g_h0[NBUOY * HID];
__device__ __half g_h1[NBUOY * HID];
__device__ __half g_h2[NBUOY * HID];
__device__ __half g_h3[NBUOY * HID];
__device__ float  g_f0[NBUOY * HID];
__device__ float  g_f1[NBUOY * HID];
__device__ float  g_embproj[NEMB * TH];

// ---------------------------------------------------------------------------
// helpers
// ---------------------------------------------------------------------------
__device__ __forceinline__ uint32_t smem_u32(const void* p) {
    uint32_t a;
    asm("{ .reg .u64 t; cvta.to.shared.u64 t, %1; cvt.u32.u64 %0, t; }" : "=r"(a) : "l"(p));
    return a;
}
#define SWZ(b) ((b) ^ (((b) >> 3) & 0x70))

#define CP_ASYNC16(dst, src) \
    asm volatile("cp.async.cg.shared.global [%0], [%1], 16;" :: "r"(dst), "l"(src) : "memory")

__device__ __forceinline__ void ldsm_x4(uint32_t r[4], uint32_t addr) {
    asm volatile("ldmatrix.sync.aligned.m8n8.x4.shared.b16 {%0,%1,%2,%3}, [%4];"
                 : "=r"(r[0]), "=r"(r[1]), "=r"(r[2]), "=r"(r[3]) : "r"(addr));
}

__device__ __forceinline__ void mma16816(float c[4], const uint32_t a[4], const uint32_t b[2]) {
    asm volatile("mma.sync.aligned.m16n8k16.row.col.f32.f16.f16.f32 "
                 "{%0,%1,%2,%3},{%4,%5,%6,%7},{%8,%9},{%0,%1,%2,%3};"
                 : "+f"(c[0]), "+f"(c[1]), "+f"(c[2]), "+f"(c[3])
                 : "r"(a[0]), "r"(a[1]), "r"(a[2]), "r"(a[3]), "r"(b[0]), "r"(b[1]));
}

// ---------------------------------------------------------------------------
// chunk loader: one BK=128 chunk (A 128x128, 3 B gate tiles 32x128), or a
// half chunk (K=64) for the obs tail.
// Stage layout: A @0: [ksub][row][128B]; B gate g @32768+g*8192: [ksub][row][128B]
// ---------------------------------------------------------------------------
template <bool GH, bool GI>
__device__ __forceinline__ void load_chunk(
    int c, uint32_t sbase,
    const __half* __restrict__ hA, const __half* __restrict__ giA,
    const __half* __restrict__ obs, int obsWcol,
    const __half* __restrict__ Whh, const __half* __restrict__ Wih,
    int iBase, int jBase, int tid)
{
    constexpr int NCGH = GH ? 8 : 0;
    constexpr int NCGI = GI ? 8 : 0;
    constexpr int NC   = NCGH + NCGI + 1;

    const __half* Ap; int lda, acol; const __half* Bp; int ldb, bcol;
    bool half = false;
    if (GH && c < NCGH) {
        Ap = hA;  lda = 1024; acol = c * 128;
        Bp = Whh; ldb = 1024; bcol = c * 128;
    } else if (GI && c < NCGH + NCGI) {
        int k = c - NCGH;
        Ap = giA; lda = 1024; acol = k * 128;
        Bp = Wih; ldb = 1088; bcol = k * 128;
    } else {
        Ap = obs; lda = 512;  acol = 0;
        Bp = Wih; ldb = 1088; bcol = obsWcol;
        half = true;
    }
    (void)NC;
    uint32_t sb = sbase + (c & 1) * STAGE_BYTES;

    // A: up to 2048 x 16B (full) or 1024 (half); 256 threads
    const int nA = half ? 1024 : 2048;
    #pragma unroll
    for (int p = 0; p < 8; ++p) {
        int q = tid + (p << 8);
        if (q < nA) {
            int ksub = q >> 10;
            int rem  = q & 1023;
            int row  = rem >> 3, c8 = rem & 7;
            const __half* src = Ap + (size_t)(iBase + row) * lda + acol + ksub * 64 + c8 * 8;
            CP_ASYNC16(sb + ksub * 16384 + SWZ(row * 128 + c8 * 16), src);
        }
    }
    // B: up to 1536 x 16B (full) or 768 (half)
    const int nB = half ? 768 : 1536;
    #pragma unroll
    for (int p = 0; p < 6; ++p) {
        int q = tid + (p << 8);
        if (q < nB) {
            int ksub = q >= 768 ? 1 : 0;
            int rem  = q - ksub * 768;
            int g  = rem >> 8;
            int rr = (rem >> 3) & 31, c8 = rem & 7;
            const __half* src = Bp + (size_t)(g * 1024 + jBase + rr) * ldb + bcol + ksub * 64 + c8 * 8;
            CP_ASYNC16(sb + 32768 + g * 8192 + ksub * 4096 + SWZ(rr * 128 + c8 * 16), src);
        }
    }
    asm volatile("cp.async.commit_group;" ::: "memory");
}

// ---------------------------------------------------------------------------
// Fused GRU step (fp16 mma.sync, BK=128 double-buffer, 2 CTAs/SM)
// ---------------------------------------------------------------------------
template <bool GH, bool GI, bool EMB, bool WR>
__global__ void __launch_bounds__(256, 2) gru_fp16_kernel(
    const __half* __restrict__ hA,
    const __half* __restrict__ giA,
    const __half* __restrict__ obs,   // pre-offset by t*64, lda=512
    int obsWcol,
    const __half* __restrict__ Whh,
    const __half* __restrict__ Wih,
    const float* __restrict__ b_ih,
    const float* __restrict__ b_hh,
    const int* __restrict__ ids,
    const float* __restrict__ hprev,
    float* __restrict__ hout,
    __half* __restrict__ hrnd)
{
    extern __shared__ __align__(1024) unsigned char smem[];
    constexpr int NCGH = GH ? 8 : 0;
    constexpr int NCGI = GI ? 8 : 0;
    constexpr int NC   = NCGH + NCGI + 1;

    const int tid  = threadIdx.x;
    const int lane = tid & 31;
    const int warp = tid >> 5;
    const int wm   = warp & 3;   // M: 4 warps x 32 rows
    const int wn   = warp >> 2;  // N: 2 warps x 16 cols (per gate)
    const int iBase = blockIdx.y * BM;
    const int jBase = blockIdx.x * BNG;
    const uint32_t sbase = smem_u32(smem);

    // ldmatrix lane geometry
    const int a_row = wm * 32 + ((lane >> 3) & 1) * 8 + (lane & 7);
    const int a_kx  = ((lane >> 4) & 1) * 16;
    const uint32_t a_xor = (uint32_t)((a_row & 7) << 4);
    const int b_row = wn * 16 + ((lane >> 4) & 1) * 8 + (lane & 7);
    const int b_kx  = ((lane >> 3) & 1) * 16;
    const uint32_t b_xor = (uint32_t)((b_row & 7) << 4);

    float aR[2][2][4] = {}, aZ[2][2][4] = {}, aNi[2][2][4] = {}, aNh[2][2][4] = {};

    load_chunk<GH, GI>(0, sbase, hA, giA, obs, obsWcol, Whh, Wih, iBase, jBase, tid);

    #pragma unroll 1
    for (int c = 0; c < NC; ++c) {
        asm volatile("cp.async.wait_group 0;" ::: "memory");
        __syncthreads();
        if (c + 1 < NC)
            load_chunk<GH, GI>(c + 1, sbase, hA, giA, obs, obsWcol, Whh, Wih, iBase, jBase, tid);

        const bool useNh = GH && (c < NCGH);
        const int  nsub  = (c == NC - 1) ? 1 : 2;
        uint32_t sb = sbase + (c & 1) * STAGE_BYTES;

        #pragma unroll 1
        for (int ksub = 0; ksub < nsub; ++ksub) {
            uint32_t sa = sb + ksub * 16384;
            uint32_t sB = sb + 32768 + ksub * 4096;
            #pragma unroll
            for (int k16 = 0; k16 < 4; ++k16) {
                uint32_t a[2][4];
                #pragma unroll
                for (int mt = 0; mt < 2; ++mt)
                    ldsm_x4(a[mt], sa + (uint32_t)((a_row + mt * 16) * 128) +
                                   ((uint32_t)(k16 * 32 + a_kx) ^ a_xor));
                #pragma unroll
                for (int g = 0; g < 3; ++g) {
                    uint32_t r[4];
                    ldsm_x4(r, sB + g * 8192 + (uint32_t)(b_row * 128) +
                               ((uint32_t)(k16 * 32 + b_kx) ^ b_xor));
                    uint32_t bb0[2] = { r[0], r[1] };
                    uint32_t bb1[2] = { r[2], r[3] };
                    float (*acc)[2][4] = (g == 0) ? aR : (g == 1) ? aZ : (useNh ? aNh : aNi);
                    #pragma unroll
                    for (int mt = 0; mt < 2; ++mt) {
                        mma16816(acc[mt][0], a[mt], bb0);
                        mma16816(acc[mt][1], a[mt], bb1);
                    }
                }
            }
        }
    }

    // -----------------------------------------------------------------------
    // Epilogue: gates + blend, direct coalesced stores
    // -----------------------------------------------------------------------
    const int row0 = iBase + wm * 32 + (lane >> 2);
    const int col0 = jBase + wn * 16 + (lane & 3) * 2;
    #pragma unroll
    for (int mt = 0; mt < 2; ++mt) {
        #pragma unroll
        for (int rh = 0; rh < 2; ++rh) {
            const int i = row0 + mt * 16 + rh * 8;
            const float* ep = EMB ? (g_embproj + (size_t)ids[i] * TH) : b_ih;
            #pragma unroll
            for (int nt = 0; nt < 2; ++nt) {
                const int jg = col0 + nt * 8;
                float2 gr  = *(const float2*)&ep[jg];
                float2 gz  = *(const float2*)&ep[jg + 1024];
                float2 gn  = *(const float2*)&ep[jg + 2048];
                float2 bhr = *(const float2*)&b_hh[jg];
                float2 bhz = *(const float2*)&b_hh[jg + 1024];
                float2 bhn = *(const float2*)&b_hh[jg + 2048];
                float2 hp = GH ? *(const float2*)&hprev[(size_t)i * 1024 + jg]
                               : make_float2(0.f, 0.f);
                float2 hv;
                #pragma unroll
                for (int e = 0; e < 2; ++e) {
                    float rp = aR[mt][nt][rh * 2 + e] + (e ? gr.y : gr.x) + (e ? bhr.y : bhr.x);
                    float zp = aZ[mt][nt][rh * 2 + e] + (e ? gz.y : gz.x) + (e ? bhz.y : bhz.x);
                    float ni = aNi[mt][nt][rh * 2 + e] + (e ? gn.y : gn.x);
                    float nh = (GH ? aNh[mt][nt][rh * 2 + e] : 0.f) + (e ? bhn.y : bhn.x);
                    float r = 1.f / (1.f + expf(-rp));
                    float z = 1.f / (1.f + expf(-zp));
                    float n = tanhf(ni + r * nh);
                    float h = (1.f - z) * n + z * (e ? hp.y : hp.x);
                    if (e) hv.y = h; else hv.x = h;
                }
                *(float2*)&hout[(size_t)i * 1024 + jg] = hv;
                if (WR)
                    *(__half2*)&hrnd[(size_t)i * 1024 + jg] = __floats2half2_rn(hv.x, hv.y);
            }
        }
    }
}

// ---------------------------------------------------------------------------
// Prep: fp32 -> fp16 conversion (n divisible by 4)
// ---------------------------------------------------------------------------
__global__ void __launch_bounds__(256) f2h_kernel(
    const float4* __restrict__ src, __half2* __restrict__ dst, int n4)
{
    int i = blockIdx.x * 256 + threadIdx.x;
    if (i < n4) {
        float4 v = src[i];
        dst[i * 2 + 0] = __floats2half2_rn(v.x, v.y);
        dst[i * 2 + 1] = __floats2half2_rn(v.z, v.w);
    }
}

// ---------------------------------------------------------------------------
// Prep: embproj[e][j] = b_ih[j] + sum_k emb[e][k] * W_ih[j][64+k]   (fp32)
// ---------------------------------------------------------------------------
__global__ void __launch_bounds__(128) embproj_kernel(
    const float* __restrict__ emb,
    const float* __restrict__ Wih,
    const float* __restrict__ b_ih)
{
    __shared__ float se[5][1024];
    const int tid = threadIdx.x;
    const int eg = blockIdx.y;               // 20 groups of 5 embeddings
    const int j = blockIdx.x * 128 + tid;

    for (int q = tid; q < 5 * 256; q += 128) {
        int e = q >> 8;
        int k = (q & 255) * 4;
        float4 v = *(const float4*)&emb[(size_t)(eg * 5 + e) * 1024 + k];
        se[e][k] = v.x; se[e][k + 1] = v.y; se[e][k + 2] = v.z; se[e][k + 3] = v.w;
    }
    __syncthreads();

    float acc[5];
    #pragma unroll
    for (int e = 0; e < 5; ++e) acc[e] = 0.f;
    const float* w = Wih + (size_t)j * INP + 64;
    for (int k = 0; k < 1024; k += 4) {
        float4 wv = *(const float4*)&w[k];
        #pragma unroll
        for (int e = 0; e < 5; ++e)
            acc[e] += wv.x * se[e][k] + wv.y * se[e][k + 1] +
                      wv.z * se[e][k + 2] + wv.w * se[e][k + 3];
    }
    float b = b_ih[j];
    #pragma unroll
    for (int e = 0; e < 5; ++e)
        g_embproj[(size_t)(eg * 5 + e) * TH + j] = b + acc[e];
}

// ---------------------------------------------------------------------------
extern "C" void kernel_launch(void* const* d_in, const int* in_sizes, int n_in,
                              void* d_out, int out_size)
{
    const float* obs  = (const float*)d_in[0];  // (16384, 8, 64)
    const int*   ids  = (const int*)  d_in[1];  // (16384,)
    const float* emb  = (const float*)d_in[2];  // (100, 1024)
    const float* Wih  = (const float*)d_in[3];  // (3072, 1088)
    const float* Whh  = (const float*)d_in[4];  // (3072, 1024)
    const float* b_ih = (const float*)d_in[5];  // (3072,)
    const float* b_hh = (const float*)d_in[6];  // (3072,)
    float* out = (float*)d_out;                 // (1, 16384, 1024)

    void *pwi, *pwh, *pob, *ph0, *ph1, *ph2, *ph3, *pf0, *pf1;
    cudaGetSymbolAddress(&pwi, g_wih_h);
    cudaGetSymbolAddress(&pwh, g_whh_h);
    cudaGetSymbolAddress(&pob, g_obs_h);
    cudaGetSymbolAddress(&ph0, g_h0);
    cudaGetSymbolAddress(&ph1, g_h1);
    cudaGetSymbolAddress(&ph2, g_h2);
    cudaGetSymbolAddress(&ph3, g_h3);
    cudaGetSymbolAddress(&pf0, g_f0);
    cudaGetSymbolAddress(&pf1, g_f1);
    __half *wih_h = (__half*)pwi, *whh_h = (__half*)pwh, *obs_h = (__half*)pob;
    __half *h0 = (__half*)ph0, *h1 = (__half*)ph1, *h2 = (__half*)ph2, *h3 = (__half*)ph3;
    float *f0 = (float*)pf0, *f1 = (float*)pf1;

    cudaFuncSetAttribute(gru_fp16_kernel<false, false, true,  true >, cudaFuncAttributeMaxDynamicSharedMemorySize, SMEM_BYTES);
    cudaFuncSetAttribute(gru_fp16_kernel<true,  false, true,  true >, cudaFuncAttributeMaxDynamicSharedMemorySize, SMEM_BYTES);
    cudaFuncSetAttribute(gru_fp16_kernel<true,  true,  false, true >, cudaFuncAttributeMaxDynamicSharedMemorySize, SMEM_BYTES);
    cudaFuncSetAttribute(gru_fp16_kernel<true,  true,  false, false>, cudaFuncAttributeMaxDynamicSharedMemorySize, SMEM_BYTES);

    // Prep
    f2h_kernel<<<(TH * INP / 4 + 255) / 256, 256>>>((const float4*)Wih, (__half2*)wih_h, TH * INP / 4);
    f2h_kernel<<<(TH * HID / 4 + 255) / 256, 256>>>((const float4*)Whh, (__half2*)whh_h, TH * HID / 4);
    f2h_kernel<<<(NBUOY * 512 / 4 + 255) / 256, 256>>>((const float4*)obs, (__half2*)obs_h, NBUOY * 512 / 4);
    embproj_kernel<<<dim3(TH / 128, 20), 128>>>(emb, Wih, b_ih);

    dim3 gs(HID / BNG, NBUOY / BM);  // (32, 128)

    // step 0: h=0; gi = obs0 @ Wih[:, :64]^T + embproj[id]
    gru_fp16_kernel<false, false, true, true><<<gs, 256, SMEM_BYTES>>>(
        nullptr, nullptr, obs_h + 0, 0, whh_h, wih_h, b_ih, b_hh, ids, nullptr, f0, h0);
    // step 1
    gru_fp16_kernel<true, false, true, true><<<gs, 256, SMEM_BYTES>>>(
        h0, nullptr, obs_h + 64, 0, whh_h, wih_h, b_ih, b_hh, ids, f0, f1, h1);
    // step 2
    gru_fp16_kernel<true, false, true, true><<<gs, 256, SMEM_BYTES>>>(
        h1, nullptr, obs_h + 128, 0, whh_h, wih_h, b_ih, b_hh, ids, f1, f0, h2);
    // step 3: x = [h0, obs1]
    gru_fp16_kernel<true, true, false, true><<<gs, 256, SMEM_BYTES>>>(
        h2, h0, obs_h + 64, 1024, whh_h, wih_h, b_ih, b_hh, ids, f0, f1, h3);
    // step 4: x = [h3, obs2] -> final output
    gru_fp16_kernel<true, true, false, false><<<gs, 256, SMEM_BYTES>>>(
        h3, h3, obs_h + 128, 1024, whh_h, wih_h, b_ih, b_hh, ids, f1, out, nullptr);
}

// round 13
// speedup vs baseline: 1.0078x; 1.0078x over previous
#include <cuda_runtime.h>
#include <cuda_fp16.h>
#include <cstdint>
#include <math.h>

#define NBUOY 16384
#define HID   1024
#define TH    3072
#define INP   1088
#define NEMB  100

// Tiles
#define BM  128
#define BNG 32     // per-gate N tile (3 gates -> 96 output cols per CTA)
#define BK  64

// SMEM: 3 stages x (A 16KB + up to 6 B gate tiles x 4KB) = 3 x 40960
#define STAGE_BYTES 40960
#define SMEM_BYTES  (3 * STAGE_BYTES)

// ---------------------------------------------------------------------------
// Scratch (device globals)
// ---------------------------------------------------------------------------
__device__ __half g_wih_h[TH * INP];
__device__ __half g_whh_h[TH * HID];
__device__ __half g_obs_h[NBUOY * 512];
__device__ __half g_h0[NBUOY * HID];
__device__ __half g_h1[NBUOY * HID];
__device__ __half g_h2[NBUOY * HID];
__device__ __half g_h3[NBUOY * HID];
__device__ float  g_f0[NBUOY * HID];
__device__ float  g_f1[NBUOY * HID];
__device__ float  g_embproj[NEMB * TH];

// ---------------------------------------------------------------------------
// helpers
// ---------------------------------------------------------------------------
__device__ __forceinline__ uint32_t smem_u32(const void* p) {
    uint32_t a;
    asm("{ .reg .u64 t; cvta.to.shared.u64 t, %1; cvt.u32.u64 %0, t; }" : "=r"(a) : "l"(p));
    return a;
}
#define SWZ(b) ((b) ^ (((b) >> 3) & 0x70))

#define CP_ASYNC16(dst, src) \
    asm volatile("cp.async.cg.shared.global [%0], [%1], 16;" :: "r"(dst), "l"(src) : "memory")

__device__ __forceinline__ void ldsm_x4(uint32_t r[4], uint32_t addr) {
    asm volatile("ldmatrix.sync.aligned.m8n8.x4.shared.b16 {%0,%1,%2,%3}, [%4];"
                 : "=r"(r[0]), "=r"(r[1]), "=r"(r[2]), "=r"(r[3]) : "r"(addr));
}

__device__ __forceinline__ void mma16816(float c[4], const uint32_t a[4], const uint32_t b[2]) {
    asm volatile("mma.sync.aligned.m16n8k16.row.col.f32.f16.f16.f32 "
                 "{%0,%1,%2,%3},{%4,%5,%6,%7},{%8,%9},{%0,%1,%2,%3};"
                 : "+f"(c[0]), "+f"(c[1]), "+f"(c[2]), "+f"(c[3])
                 : "r"(a[0]), "r"(a[1]), "r"(a[2]), "r"(a[3]), "r"(b[0]), "r"(b[1]));
}

// ---------------------------------------------------------------------------
// chunk loader: one K-chunk. Stage layout: A @0 (128x128B), gate g @16384+g*4096.
// Normal chunks: 3 B gate tiles. SHA shared chunks (c<16): 6 gate tiles
// (Whh g=0..2, Wih g=3..5) sharing one A tile.
// ---------------------------------------------------------------------------
template <bool GH, bool GI, bool SHA>
__device__ __forceinline__ void load_chunk(
    int c, uint32_t sbase,
    const __half* __restrict__ hA, const __half* __restrict__ giA,
    const __half* __restrict__ obs, int obsWcol,
    const __half* __restrict__ Whh, const __half* __restrict__ Wih,
    int iBase, int jBase, int tid)
{
    constexpr int NCGH = (GH && !SHA) ? 16 : 0;
    constexpr int NCGI = (GI && !SHA) ? 16 : 0;
    uint32_t sb = sbase + (c % 3) * STAGE_BYTES;

    const bool shared6 = SHA && (c < 16);
    const __half* Ap; int lda, acol; const __half* Bp; int ldb, bcol;
    if (shared6) {
        Ap = hA;  lda = 1024; acol = c * 64;
        Bp = Whh; ldb = 1024; bcol = c * 64;
    } else if (!SHA && GH && c < NCGH) {
        Ap = hA;  lda = 1024; acol = c * 64;
        Bp = Whh; ldb = 1024; bcol = c * 64;
    } else if (!SHA && GI && c < NCGH + NCGI) {
        int k = c - NCGH;
        Ap = giA; lda = 1024; acol = k * 64;
        Bp = Wih; ldb = 1088; bcol = k * 64;
    } else {
        Ap = obs; lda = 512;  acol = 0;
        Bp = Wih; ldb = 1088; bcol = obsWcol;
    }

    // A tile: 128 rows x 128B = 1024 x 16B ; 256 threads -> 4 iters
    #pragma unroll
    for (int p = 0; p < 4; ++p) {
        int q = tid + (p << 8);
        int row = q >> 3, c8 = q & 7;
        const __half* src = Ap + (size_t)(iBase + row) * lda + acol + c8 * 8;
        CP_ASYNC16(sb + SWZ(row * 128 + c8 * 16), src);
    }
    if (shared6) {
        // 6 gates x 32 rows x 128B = 1536 x 16B -> 6 iters
        #pragma unroll
        for (int p = 0; p < 6; ++p) {
            int q = tid + (p << 8);
            int g = q >> 8, rr = (q >> 3) & 31, c8 = q & 7;
            const __half* src = (g < 3)
                ? (Whh + (size_t)(g * 1024 + jBase + rr) * 1024 + c * 64 + c8 * 8)
                : (Wih + (size_t)((g - 3) * 1024 + jBase + rr) * 1088 + c * 64 + c8 * 8);
            CP_ASYNC16(sb + 16384 + g * 4096 + SWZ(rr * 128 + c8 * 16), src);
        }
    } else {
        // 3 gates x 32 rows x 128B = 768 x 16B -> 3 iters
        #pragma unroll
        for (int p = 0; p < 3; ++p) {
            int q = tid + (p << 8);
            int g = q >> 8, rr = (q >> 3) & 31, c8 = q & 7;
            const __half* src = Bp + (size_t)(g * 1024 + jBase + rr) * ldb + bcol + c8 * 8;
            CP_ASYNC16(sb + 16384 + g * 4096 + SWZ(rr * 128 + c8 * 16), src);
        }
    }
    asm volatile("cp.async.commit_group;" ::: "memory");
}

// ---------------------------------------------------------------------------
// Fused GRU step (fp16 mma.sync, cp.async 3-stage pipeline, 2 CTAs/SM)
// ---------------------------------------------------------------------------
template <bool GH, bool GI, bool SHA, bool EMB, bool WR>
__global__ void __launch_bounds__(256, 2) gru_fp16_kernel(
    const __half* __restrict__ hA,
    const __half* __restrict__ giA,
    const __half* __restrict__ obs,   // pre-offset by t*64, lda=512
    int obsWcol,
    const __half* __restrict__ Whh,
    const __half* __restrict__ Wih,
    const float* __restrict__ b_ih,
    const float* __restrict__ b_hh,
    const int* __restrict__ ids,
    const float* __restrict__ hprev,
    float* __restrict__ hout,
    __half* __restrict__ hrnd)
{
    extern __shared__ __align__(1024) unsigned char smem[];
    constexpr int NCGH = (GH && !SHA) ? 16 : 0;
    constexpr int NCGI = (GI && !SHA) ? 16 : 0;
    constexpr int NC = SHA ? 17 : (NCGH + NCGI + 1);

    const int tid  = threadIdx.x;
    const int lane = tid & 31;
    const int warp = tid >> 5;
    const int wm   = warp & 3;   // M: 4 warps x 32 rows
    const int wn   = warp >> 2;  // N: 2 warps x 16 cols (per gate)
    const int iBase = blockIdx.y * BM;
    const int jBase = blockIdx.x * BNG;
    const uint32_t sbase = smem_u32(smem);

    // ldmatrix lane geometry
    const int a_row = wm * 32 + ((lane >> 3) & 1) * 8 + (lane & 7);
    const int a_kx  = ((lane >> 4) & 1) * 16;
    const uint32_t a_xor = (uint32_t)((a_row & 7) << 4);
    const int b_row = wn * 16 + ((lane >> 4) & 1) * 8 + (lane & 7);
    const int b_kx  = ((lane >> 3) & 1) * 16;
    const uint32_t b_xor = (uint32_t)((b_row & 7) << 4);

    float aR[2][2][4] = {}, aZ[2][2][4] = {}, aNi[2][2][4] = {}, aNh[2][2][4] = {};

    int loaded = 0;
    #pragma unroll
    for (; loaded < 2 && loaded < NC; ++loaded)
        load_chunk<GH, GI, SHA>(loaded, sbase, hA, giA, obs, obsWcol, Whh, Wih, iBase, jBase, tid);

    #pragma unroll 1
    for (int c = 0; c < NC; ++c) {
        if (loaded == c + 2) asm volatile("cp.async.wait_group 1;" ::: "memory");
        else                 asm volatile("cp.async.wait_group 0;" ::: "memory");
        __syncthreads();
        if (loaded < NC) {
            load_chunk<GH, GI, SHA>(loaded, sbase, hA, giA, obs, obsWcol, Whh, Wih, iBase, jBase, tid);
            ++loaded;
        }
        const bool shared6 = SHA && (c < 16);
        const bool useNh   = shared6 || (!SHA && GH && c < NCGH);
        uint32_t sb = sbase + (c % 3) * STAGE_BYTES;

        #pragma unroll
        for (int k16 = 0; k16 < 4; ++k16) {
            uint32_t a[2][4];
            #pragma unroll
            for (int mt = 0; mt < 2; ++mt)
                ldsm_x4(a[mt], sb + (uint32_t)((a_row + mt * 16) * 128) +
                               ((uint32_t)(k16 * 32 + a_kx) ^ a_xor));
            #pragma unroll
            for (int g = 0; g < 3; ++g) {
                uint32_t r[4];
                ldsm_x4(r, sb + 16384 + g * 4096 + (uint32_t)(b_row * 128) +
                           ((uint32_t)(k16 * 32 + b_kx) ^ b_xor));
                uint32_t bb0[2] = { r[0], r[1] };
                uint32_t bb1[2] = { r[2], r[3] };
                float (*acc)[2][4] = (g == 0) ? aR : (g == 1) ? aZ : (useNh ? aNh : aNi);
                #pragma unroll
                for (int mt = 0; mt < 2; ++mt) {
                    mma16816(acc[mt][0], a[mt], bb0);
                    mma16816(acc[mt][1], a[mt], bb1);
                }
            }
            if (SHA && shared6) {
                #pragma unroll
                for (int g = 3; g < 6; ++g) {
                    uint32_t r[4];
                    ldsm_x4(r, sb + 16384 + g * 4096 + (uint32_t)(b_row * 128) +
                               ((uint32_t)(k16 * 32 + b_kx) ^ b_xor));
                    uint32_t bb0[2] = { r[0], r[1] };
                    uint32_t bb1[2] = { r[2], r[3] };
                    float (*acc)[2][4] = (g == 3) ? aR : (g == 4) ? aZ : aNi;
                    #pragma unroll
                    for (int mt = 0; mt < 2; ++mt) {
                        mma16816(acc[mt][0], a[mt], bb0);
                        mma16816(acc[mt][1], a[mt], bb1);
                    }
                }
            }
        }
    }

    // -----------------------------------------------------------------------
    // Epilogue: gates + blend, direct coalesced stores
    // -----------------------------------------------------------------------
    const int row0 = iBase + wm * 32 + (lane >> 2);
    const int col0 = jBase + wn * 16 + (lane & 3) * 2;
    #pragma unroll
    for (int mt = 0; mt < 2; ++mt) {
        #pragma unroll
        for (int rh = 0; rh < 2; ++rh) {
            const int i = row0 + mt * 16 + rh * 8;
            const float* ep = EMB ? (g_embproj + (size_t)ids[i] * TH) : b_ih;
            #pragma unroll
            for (int nt = 0; nt < 2; ++nt) {
                const int jg = col0 + nt * 8;
                float2 gr  = *(const float2*)&ep[jg];
                float2 gz  = *(const float2*)&ep[jg + 1024];
                float2 gn  = *(const float2*)&ep[jg + 2048];
                float2 bhr = *(const float2*)&b_hh[jg];
                float2 bhz = *(const float2*)&b_hh[jg + 1024];
                float2 bhn = *(const float2*)&b_hh[jg + 2048];
                float2 hp = GH ? *(const float2*)&hprev[(size_t)i * 1024 + jg]
                               : make_float2(0.f, 0.f);
                float2 hv;
                #pragma unroll
                for (int e = 0; e < 2; ++e) {
                    float rp = aR[mt][nt][rh * 2 + e] + (e ? gr.y : gr.x) + (e ? bhr.y : bhr.x);
                    float zp = aZ[mt][nt][rh * 2 + e] + (e ? gz.y : gz.x) + (e ? bhz.y : bhz.x);
                    float ni = aNi[mt][nt][rh * 2 + e] + (e ? gn.y : gn.x);
                    float nh = (GH ? aNh[mt][nt][rh * 2 + e] : 0.f) + (e ? bhn.y : bhn.x);
                    float r = 1.f / (1.f + expf(-rp));
                    float z = 1.f / (1.f + expf(-zp));
                    float n = tanhf(ni + r * nh);
                    float h = (1.f - z) * n + z * (e ? hp.y : hp.x);
                    if (e) hv.y = h; else hv.x = h;
                }
                *(float2*)&hout[(size_t)i * 1024 + jg] = hv;
                if (WR)
                    *(__half2*)&hrnd[(size_t)i * 1024 + jg] = __floats2half2_rn(hv.x, hv.y);
            }
        }
    }
}

// ---------------------------------------------------------------------------
// Prep: fp32 -> fp16 conversion (n divisible by 4)
// ---------------------------------------------------------------------------
__global__ void __launch_bounds__(256) f2h_kernel(
    const float4* __restrict__ src, __half2* __restrict__ dst, int n4)
{
    int i = blockIdx.x * 256 + threadIdx.x;
    if (i < n4) {
        float4 v = src[i];
        dst[i * 2 + 0] = __floats2half2_rn(v.x, v.y);
        dst[i * 2 + 1] = __floats2half2_rn(v.z, v.w);
    }
}

// ---------------------------------------------------------------------------
// Prep: embproj[e][j] = b_ih[j] + sum_k emb[e][k] * W_ih[j][64+k]   (fp32)
// ---------------------------------------------------------------------------
__global__ void __launch_bounds__(128) embproj_kernel(
    const float* __restrict__ emb,
    const float* __restrict__ Wih,
    const float* __restrict__ b_ih)
{
    __shared__ float se[5][1024];
    const int tid = threadIdx.x;
    const int eg = blockIdx.y;               // 20 groups of 5 embeddings
    const int j = blockIdx.x * 128 + tid;

    for (int q = tid; q < 5 * 256; q += 128) {
        int e = q >> 8;
        int k = (q & 255) * 4;
        float4 v = *(const float4*)&emb[(size_t)(eg * 5 + e) * 1024 + k];
        se[e][k] = v.x; se[e][k + 1] = v.y; se[e][k + 2] = v.z; se[e][k + 3] = v.w;
    }
    __syncthreads();

    float acc[5];
    #pragma unroll
    for (int e = 0; e < 5; ++e) acc[e] = 0.f;
    const float* w = Wih + (size_t)j * INP + 64;
    for (int k = 0; k < 1024; k += 4) {
        float4 wv = *(const float4*)&w[k];
        #pragma unroll
        for (int e = 0; e < 5; ++e)
            acc[e] += wv.x * se[e][k] + wv.y * se[e][k + 1] +
                      wv.z * se[e][k + 2] + wv.w * se[e][k + 3];
    }
    float b = b_ih[j];
    #pragma unroll
    for (int e = 0; e < 5; ++e)
        g_embproj[(size_t)(eg * 5 + e) * TH + j] = b + acc[e];
}

// ---------------------------------------------------------------------------
extern "C" void kernel_launch(void* const* d_in, const int* in_sizes, int n_in,
                              void* d_out, int out_size)
{
    const float* obs  = (const float*)d_in[0];  // (16384, 8, 64)
    const int*   ids  = (const int*)  d_in[1];  // (16384,)
    const float* emb  = (const float*)d_in[2];  // (100, 1024)
    const float* Wih  = (const float*)d_in[3];  // (3072, 1088)
    const float* Whh  = (const float*)d_in[4];  // (3072, 1024)
    const float* b_ih = (const float*)d_in[5];  // (3072,)
    const float* b_hh = (const float*)d_in[6];  // (3072,)
    float* out = (float*)d_out;                 // (1, 16384, 1024)

    void *pwi, *pwh, *pob, *ph0, *ph1, *ph2, *ph3, *pf0, *pf1;
    cudaGetSymbolAddress(&pwi, g_wih_h);
    cudaGetSymbolAddress(&pwh, g_whh_h);
    cudaGetSymbolAddress(&pob, g_obs_h);
    cudaGetSymbolAddress(&ph0, g_h0);
    cudaGetSymbolAddress(&ph1, g_h1);
    cudaGetSymbolAddress(&ph2, g_h2);
    cudaGetSymbolAddress(&ph3, g_h3);
    cudaGetSymbolAddress(&pf0, g_f0);
    cudaGetSymbolAddress(&pf1, g_f1);
    __half *wih_h = (__half*)pwi, *whh_h = (__half*)pwh, *obs_h = (__half*)pob;
    __half *h0 = (__half*)ph0, *h1 = (__half*)ph1, *h2 = (__half*)ph2, *h3 = (__half*)ph3;
    float *f0 = (float*)pf0, *f1 = (float*)pf1;

    cudaFuncSetAttribute(gru_fp16_kernel<false, false, false, true,  true >, cudaFuncAttributeMaxDynamicSharedMemorySize, SMEM_BYTES);
    cudaFuncSetAttribute(gru_fp16_kernel<true,  false, false, true,  true >, cudaFuncAttributeMaxDynamicSharedMemorySize, SMEM_BYTES);
    cudaFuncSetAttribute(gru_fp16_kernel<true,  true,  false, false, true >, cudaFuncAttributeMaxDynamicSharedMemorySize, SMEM_BYTES);
    cudaFuncSetAttribute(gru_fp16_kernel<true,  true,  true,  false, false>, cudaFuncAttributeMaxDynamicSharedMemorySize, SMEM_BYTES);

    // Prep
    f2h_kernel<<<(TH * INP / 4 + 255) / 256, 256>>>((const float4*)Wih, (__half2*)wih_h, TH * INP / 4);
    f2h_kernel<<<(TH * HID / 4 + 255) / 256, 256>>>((const float4*)Whh, (__half2*)whh_h, TH * HID / 4);
    f2h_kernel<<<(NBUOY * 512 / 4 + 255) / 256, 256>>>((const float4*)obs, (__half2*)obs_h, NBUOY * 512 / 4);
    embproj_kernel<<<dim3(TH / 128, 20), 128>>>(emb, Wih, b_ih);

    dim3 gs(HID / BNG, NBUOY / BM);  // (32, 128)

    // step 0: h=0; gi = obs0 @ Wih[:, :64]^T + embproj[id]
    gru_fp16_kernel<false, false, false, true, true><<<gs, 256, SMEM_BYTES>>>(
        nullptr, nullptr, obs_h + 0, 0, whh_h, wih_h, b_ih, b_hh, ids, nullptr, f0, h0);
    // step 1
    gru_fp16_kernel<true, false, false, true, true><<<gs, 256, SMEM_BYTES>>>(
        h0, nullptr, obs_h + 64, 0, whh_h, wih_h, b_ih, b_hh, ids, f0, f1, h1);
    // step 2
    gru_fp16_kernel<true, false, false, true, true><<<gs, 256, SMEM_BYTES>>>(
        h1, nullptr, obs_h + 128, 0, whh_h, wih_h, b_ih, b_hh, ids, f1, f0, h2);
    // step 3: x = [h0, obs1]
    gru_fp16_kernel<true, true, false, false, true><<<gs, 256, SMEM_BYTES>>>(
        h2, h0, obs_h + 64, 1024, whh_h, wih_h, b_ih, b_hh, ids, f0, f1, h3);
    // step 4: x = [h3, obs2] -> final output (shared-A: hA == giA == h3)
    gru_fp16_kernel<true, true, true, false, false><<<gs, 256, SMEM_BYTES>>>(
        h3, h3, obs_h + 128, 1024, whh_h, wih_h, b_ih, b_hh, ids, f1, out, nullptr);
}

// round 14
// speedup vs baseline: 1.2589x; 1.2492x over previous
#include <cuda_runtime.h>
#include <cuda_fp16.h>
#include <cstdint>
#include <math.h>

#define NBUOY 16384
#define HID   1024
#define TH    3072
#define INP   1088
#define NEMB  100

// Tiles
#define BM  128
#define BNG 32     // per-gate N tile (3 gates -> 96 output cols per CTA)
#define BK  64

// SMEM: 4 stages x (A 16KB + 3x B 4KB) = 4 x 28672 = 114688 (2 CTAs/SM = 224KB)
#define STAGE_BYTES 28672
#define NSTAGE 4
#define SMEM_BYTES  (NSTAGE * STAGE_BYTES)

// ---------------------------------------------------------------------------
// Scratch (device globals)
// ---------------------------------------------------------------------------
__device__ __half g_wih_h[TH * INP];
__device__ __half g_whh_h[TH * HID];
__device__ __half g_obs_h[NBUOY * 512];
__device__ __half g_h0[NBUOY * HID];
__device__ __half g_h1[NBUOY * HID];
__device__ __half g_h2[NBUOY * HID];
__device__ __half g_h3[NBUOY * HID];
__device__ float  g_f0[NBUOY * HID];
__device__ float  g_f1[NBUOY * HID];
__device__ float  g_embproj[NEMB * TH];

// ---------------------------------------------------------------------------
// helpers
// ---------------------------------------------------------------------------
__device__ __forceinline__ uint32_t smem_u32(const void* p) {
    uint32_t a;
    asm("{ .reg .u64 t; cvta.to.shared.u64 t, %1; cvt.u32.u64 %0, t; }" : "=r"(a) : "l"(p));
    return a;
}
#define SWZ(b) ((b) ^ (((b) >> 3) & 0x70))

#define CP_ASYNC16(dst, src) \
    asm volatile("cp.async.cg.shared.global [%0], [%1], 16;" :: "r"(dst), "l"(src) : "memory")

__device__ __forceinline__ void ldsm_x4(uint32_t r[4], uint32_t addr) {
    asm volatile("ldmatrix.sync.aligned.m8n8.x4.shared.b16 {%0,%1,%2,%3}, [%4];"
                 : "=r"(r[0]), "=r"(r[1]), "=r"(r[2]), "=r"(r[3]) : "r"(addr));
}

__device__ __forceinline__ void mma16816(float c[4], const uint32_t a[4], const uint32_t b[2]) {
    asm volatile("mma.sync.aligned.m16n8k16.row.col.f32.f16.f16.f32 "
                 "{%0,%1,%2,%3},{%4,%5,%6,%7},{%8,%9},{%0,%1,%2,%3};"
                 : "+f"(c[0]), "+f"(c[1]), "+f"(c[2]), "+f"(c[3])
                 : "r"(a[0]), "r"(a[1]), "r"(a[2]), "r"(a[3]), "r"(b[0]), "r"(b[1]));
}

// ---------------------------------------------------------------------------
// chunk loader: one K-chunk (A 128x64 fp16 + 3 B gate tiles 32x64)
// ---------------------------------------------------------------------------
template <bool GH, bool GI>
__device__ __forceinline__ void load_chunk(
    int c, uint32_t sbase,
    const __half* __restrict__ hA, const __half* __restrict__ giA,
    const __half* __restrict__ obs, int obsWcol,
    const __half* __restrict__ Whh, const __half* __restrict__ Wih,
    int iBase, int jBase, int tid)
{
    constexpr int NCGH = GH ? 16 : 0;
    constexpr int NCGI = GI ? 16 : 0;
    const __half* Ap; int lda, acol; const __half* Bp; int ldb, bcol;
    if (GH && c < NCGH) {
        Ap = hA;  lda = 1024; acol = c * 64;
        Bp = Whh; ldb = 1024; bcol = c * 64;
    } else if (GI && c < NCGH + NCGI) {
        int k = c - NCGH;
        Ap = giA; lda = 1024; acol = k * 64;
        Bp = Wih; ldb = 1088; bcol = k * 64;
    } else {
        Ap = obs; lda = 512;  acol = 0;
        Bp = Wih; ldb = 1088; bcol = obsWcol;
    }
    uint32_t sb = sbase + (c % NSTAGE) * STAGE_BYTES;
    // A: 128 rows x 128B = 1024 chunks of 16B
    #pragma unroll
    for (int p = 0; p < 4; ++p) {
        int q = tid + (p << 8);
        int row = q >> 3, c8 = q & 7;
        const __half* src = Ap + (size_t)(iBase + row) * lda + acol + c8 * 8;
        CP_ASYNC16(sb + SWZ(row * 128 + c8 * 16), src);
    }
    // B: 3 gates x 32 rows x 128B = 768 chunks
    #pragma unroll
    for (int p = 0; p < 3; ++p) {
        int q = tid + (p << 8);
        int g = q >> 8, rr = (q >> 3) & 31, c8 = q & 7;
        const __half* src = Bp + (size_t)(g * 1024 + jBase + rr) * ldb + bcol + c8 * 8;
        CP_ASYNC16(sb + 16384 + g * 4096 + SWZ(rr * 128 + c8 * 16), src);
    }
    asm volatile("cp.async.commit_group;" ::: "memory");
}

// ---------------------------------------------------------------------------
// Fused GRU step (fp16 mma.sync, 4-stage cp.async pipeline, 2 CTAs/SM)
// ---------------------------------------------------------------------------
template <bool GH, bool GI, bool EMB, bool WR>
__global__ void __launch_bounds__(256, 2) gru_fp16_kernel(
    const __half* __restrict__ hA,
    const __half* __restrict__ giA,
    const __half* __restrict__ obs,   // pre-offset by t*64, lda=512
    int obsWcol,
    const __half* __restrict__ Whh,
    const __half* __restrict__ Wih,
    const float* __restrict__ b_ih,
    const float* __restrict__ b_hh,
    const int* __restrict__ ids,
    const float* __restrict__ hprev,
    float* __restrict__ hout,
    __half* __restrict__ hrnd)
{
    extern __shared__ __align__(1024) unsigned char smem[];
    constexpr int NCGH = GH ? 16 : 0;
    constexpr int NCGI = GI ? 16 : 0;
    constexpr int NC = NCGH + NCGI + 1;

    const int tid  = threadIdx.x;
    const int lane = tid & 31;
    const int warp = tid >> 5;
    const int wm   = warp & 3;   // M: 4 warps x 32 rows
    const int wn   = warp >> 2;  // N: 2 warps x 16 cols (per gate)
    const int iBase = blockIdx.y * BM;
    const int jBase = blockIdx.x * BNG;
    const uint32_t sbase = smem_u32(smem);

    // ldmatrix lane geometry
    const int a_row = wm * 32 + ((lane >> 3) & 1) * 8 + (lane & 7);
    const int a_kx  = ((lane >> 4) & 1) * 16;
    const uint32_t a_xor = (uint32_t)((a_row & 7) << 4);
    const int b_row = wn * 16 + ((lane >> 4) & 1) * 8 + (lane & 7);
    const int b_kx  = ((lane >> 3) & 1) * 16;
    const uint32_t b_xor = (uint32_t)((b_row & 7) << 4);

    float aR[2][2][4] = {}, aZ[2][2][4] = {}, aNi[2][2][4] = {}, aNh[2][2][4] = {};

    int loaded = 0;
    #pragma unroll
    for (; loaded < 3 && loaded < NC; ++loaded)
        load_chunk<GH, GI>(loaded, sbase, hA, giA, obs, obsWcol, Whh, Wih, iBase, jBase, tid);

    #pragma unroll 1
    for (int c = 0; c < NC; ++c) {
        if      (loaded == c + 3) asm volatile("cp.async.wait_group 2;" ::: "memory");
        else if (loaded == c + 2) asm volatile("cp.async.wait_group 1;" ::: "memory");
        else                      asm volatile("cp.async.wait_group 0;" ::: "memory");
        __syncthreads();
        if (loaded < NC) {
            load_chunk<GH, GI>(loaded, sbase, hA, giA, obs, obsWcol, Whh, Wih, iBase, jBase, tid);
            ++loaded;
        }
        const bool useNh = GH && (c < NCGH);
        uint32_t sb = sbase + (c % NSTAGE) * STAGE_BYTES;

        #pragma unroll
        for (int k16 = 0; k16 < 4; ++k16) {
            uint32_t a[2][4];
            #pragma unroll
            for (int mt = 0; mt < 2; ++mt)
                ldsm_x4(a[mt], sb + (uint32_t)((a_row + mt * 16) * 128) +
                               ((uint32_t)(k16 * 32 + a_kx) ^ a_xor));
            #pragma unroll
            for (int g = 0; g < 3; ++g) {
                uint32_t r[4];
                ldsm_x4(r, sb + 16384 + g * 4096 + (uint32_t)(b_row * 128) +
                           ((uint32_t)(k16 * 32 + b_kx) ^ b_xor));
                uint32_t bb0[2] = { r[0], r[1] };
                uint32_t bb1[2] = { r[2], r[3] };
                float (*acc)[2][4] = (g == 0) ? aR : (g == 1) ? aZ : (useNh ? aNh : aNi);
                #pragma unroll
                for (int mt = 0; mt < 2; ++mt) {
                    mma16816(acc[mt][0], a[mt], bb0);
                    mma16816(acc[mt][1], a[mt], bb1);
                }
            }
        }
    }

    // -----------------------------------------------------------------------
    // Epilogue: gates + blend, direct coalesced stores
    // -----------------------------------------------------------------------
    const int row0 = iBase + wm * 32 + (lane >> 2);
    const int col0 = jBase + wn * 16 + (lane & 3) * 2;
    #pragma unroll
    for (int mt = 0; mt < 2; ++mt) {
        #pragma unroll
        for (int rh = 0; rh < 2; ++rh) {
            const int i = row0 + mt * 16 + rh * 8;
            const float* ep = EMB ? (g_embproj + (size_t)ids[i] * TH) : b_ih;
            #pragma unroll
            for (int nt = 0; nt < 2; ++nt) {
                const int jg = col0 + nt * 8;
                float2 gr  = *(const float2*)&ep[jg];
                float2 gz  = *(const float2*)&ep[jg + 1024];
                float2 gn  = *(const float2*)&ep[jg + 2048];
                float2 bhr = *(const float2*)&b_hh[jg];
                float2 bhz = *(const float2*)&b_hh[jg + 1024];
                float2 bhn = *(const float2*)&b_hh[jg + 2048];
                float2 hp = GH ? *(const float2*)&hprev[(size_t)i * 1024 + jg]
                               : make_float2(0.f, 0.f);
                float2 hv;
                #pragma unroll
                for (int e = 0; e < 2; ++e) {
                    float rp = aR[mt][nt][rh * 2 + e] + (e ? gr.y : gr.x) + (e ? bhr.y : bhr.x);
                    float zp = aZ[mt][nt][rh * 2 + e] + (e ? gz.y : gz.x) + (e ? bhz.y : bhz.x);
                    float ni = aNi[mt][nt][rh * 2 + e] + (e ? gn.y : gn.x);
                    float nh = (GH ? aNh[mt][nt][rh * 2 + e] : 0.f) + (e ? bhn.y : bhn.x);
                    float r = 1.f / (1.f + expf(-rp));
                    float z = 1.f / (1.f + expf(-zp));
                    float n = tanhf(ni + r * nh);
                    float h = (1.f - z) * n + z * (e ? hp.y : hp.x);
                    if (e) hv.y = h; else hv.x = h;
                }
                *(float2*)&hout[(size_t)i * 1024 + jg] = hv;
                if (WR)
                    *(__half2*)&hrnd[(size_t)i * 1024 + jg] = __floats2half2_rn(hv.x, hv.y);
            }
        }
    }
}

// ---------------------------------------------------------------------------
// Prep: fp32 -> fp16 conversion (n divisible by 4)
// ---------------------------------------------------------------------------
__global__ void __launch_bounds__(256) f2h_kernel(
    const float4* __restrict__ src, __half2* __restrict__ dst, int n4)
{
    int i = blockIdx.x * 256 + threadIdx.x;
    if (i < n4) {
        float4 v = src[i];
        dst[i * 2 + 0] = __floats2half2_rn(v.x, v.y);
        dst[i * 2 + 1] = __floats2half2_rn(v.z, v.w);
    }
}

// ---------------------------------------------------------------------------
// Prep: embproj[e][j] = b_ih[j] + sum_k emb[e][k] * W_ih[j][64+k]   (fp32)
// 10 embeddings per block (R1 grouping, measured faster).
// ---------------------------------------------------------------------------
__global__ void __launch_bounds__(128) embproj_kernel(
    const float* __restrict__ emb,
    const float* __restrict__ Wih,
    const float* __restrict__ b_ih)
{
    __shared__ float se[10][1024];
    const int tid = threadIdx.x;
    const int eg = blockIdx.y;               // 10 groups of 10 embeddings
    const int j = blockIdx.x * 128 + tid;

    for (int q = tid; q < 10 * 256; q += 128) {
        int e = q >> 8;
        int k = (q & 255) * 4;
        float4 v = *(const float4*)&emb[(size_t)(eg * 10 + e) * 1024 + k];
        se[e][k] = v.x; se[e][k + 1] = v.y; se[e][k + 2] = v.z; se[e][k + 3] = v.w;
    }
    __syncthreads();

    float acc[10];
    #pragma unroll
    for (int e = 0; e < 10; ++e) acc[e] = 0.f;
    const float* w = Wih + (size_t)j * INP + 64;
    for (int k = 0; k < 1024; k += 4) {
        float4 wv = *(const float4*)&w[k];
        #pragma unroll
        for (int e = 0; e < 10; ++e)
            acc[e] += wv.x * se[e][k] + wv.y * se[e][k + 1] +
                      wv.z * se[e][k + 2] + wv.w * se[e][k + 3];
    }
    float b = b_ih[j];
    #pragma unroll
    for (int e = 0; e < 10; ++e)
        g_embproj[(size_t)(eg * 10 + e) * TH + j] = b + acc[e];
}

// ---------------------------------------------------------------------------
extern "C" void kernel_launch(void* const* d_in, const int* in_sizes, int n_in,
                              void* d_out, int out_size)
{
    const float* obs  = (const float*)d_in[0];  // (16384, 8, 64)
    const int*   ids  = (const int*)  d_in[1];  // (16384,)
    const float* emb  = (const float*)d_in[2];  // (100, 1024)
    const float* Wih  = (const float*)d_in[3];  // (3072, 1088)
    const float* Whh  = (const float*)d_in[4];  // (3072, 1024)
    const float* b_ih = (const float*)d_in[5];  // (3072,)
    const float* b_hh = (const float*)d_in[6];  // (3072,)
    float* out = (float*)d_out;                 // (1, 16384, 1024)

    void *pwi, *pwh, *pob, *ph0, *ph1, *ph2, *ph3, *pf0, *pf1;
    cudaGetSymbolAddress(&pwi, g_wih_h);
    cudaGetSymbolAddress(&pwh, g_whh_h);
    cudaGetSymbolAddress(&pob, g_obs_h);
    cudaGetSymbolAddress(&ph0, g_h0);
    cudaGetSymbolAddress(&ph1, g_h1);
    cudaGetSymbolAddress(&ph2, g_h2);
    cudaGetSymbolAddress(&ph3, g_h3);
    cudaGetSymbolAddress(&pf0, g_f0);
    cudaGetSymbolAddress(&pf1, g_f1);
    __half *wih_h = (__half*)pwi, *whh_h = (__half*)pwh, *obs_h = (__half*)pob;
    __half *h0 = (__half*)ph0, *h1 = (__half*)ph1, *h2 = (__half*)ph2, *h3 = (__half*)ph3;
    float *f0 = (float*)pf0, *f1 = (float*)pf1;

    cudaFuncSetAttribute(gru_fp16_kernel<false, false, true,  true >, cudaFuncAttributeMaxDynamicSharedMemorySize, SMEM_BYTES);
    cudaFuncSetAttribute(gru_fp16_kernel<true,  false, true,  true >, cudaFuncAttributeMaxDynamicSharedMemorySize, SMEM_BYTES);
    cudaFuncSetAttribute(gru_fp16_kernel<true,  true,  false, true >, cudaFuncAttributeMaxDynamicSharedMemorySize, SMEM_BYTES);
    cudaFuncSetAttribute(gru_fp16_kernel<true,  true,  false, false>, cudaFuncAttributeMaxDynamicSharedMemorySize, SMEM_BYTES);

    // Prep
    f2h_kernel<<<(TH * INP / 4 + 255) / 256, 256>>>((const float4*)Wih, (__half2*)wih_h, TH * INP / 4);
    f2h_kernel<<<(TH * HID / 4 + 255) / 256, 256>>>((const float4*)Whh, (__half2*)whh_h, TH * HID / 4);
    f2h_kernel<<<(NBUOY * 512 / 4 + 255) / 256, 256>>>((const float4*)obs, (__half2*)obs_h, NBUOY * 512 / 4);
    embproj_kernel<<<dim3(TH / 128, 10), 128>>>(emb, Wih, b_ih);

    dim3 gs(HID / BNG, NBUOY / BM);  // (32, 128)

    // step 0: h=0; gi = obs0 @ Wih[:, :64]^T + embproj[id]
    gru_fp16_kernel<false, false, true, true><<<gs, 256, SMEM_BYTES>>>(
        nullptr, nullptr, obs_h + 0, 0, whh_h, wih_h, b_ih, b_hh, ids, nullptr, f0, h0);
    // step 1
    gru_fp16_kernel<true, false, true, true><<<gs, 256, SMEM_BYTES>>>(
        h0, nullptr, obs_h + 64, 0, whh_h, wih_h, b_ih, b_hh, ids, f0, f1, h1);
    // step 2
    gru_fp16_kernel<true, false, true, true><<<gs, 256, SMEM_BYTES>>>(
        h1, nullptr, obs_h + 128, 0, whh_h, wih_h, b_ih, b_hh, ids, f1, f0, h2);
    // step 3: x = [h0, obs1]
    gru_fp16_kernel<true, true, false, true><<<gs, 256, SMEM_BYTES>>>(
        h2, h0, obs_h + 64, 1024, whh_h, wih_h, b_ih, b_hh, ids, f0, f1, h3);
    // step 4: x = [h3, obs2] -> final output
    gru_fp16_kernel<true, true, false, false><<<gs, 256, SMEM_BYTES>>>(
        h3, h3, obs_h + 128, 1024, whh_h, wih_h, b_ih, b_hh, ids, f1, out, nullptr);
}

// round 16
// speedup vs baseline: 1.4834x; 1.1783x over previous
#include <cuda_runtime.h>
#include <cuda_fp16.h>
#include <cstdint>
#include <math.h>

#define NBUOY 16384
#define HID   1024
#define TH    3072
#define INP   1088
#define NEMB  100

// Tiles
#define BM  128
#define BNG 32     // per-gate N tile (3 gates -> 96 output cols per CTA)
#define BK  64

// Normal kernel: 4 stages x (A 16KB + 3x B 4KB) = 4 x 28672 = 114688
#define STAGE_BYTES 28672
#define NSTAGE 4
#define SMEM_BYTES  (NSTAGE * STAGE_BYTES)

// Combined (step-4) kernel: 3 stages x (A 16KB + 4x B 4KB) = 3 x 32768 = 98304
#define STAGE_C 32768
#define SMEM_C  (3 * STAGE_C)

// ---------------------------------------------------------------------------
// Scratch (device globals)
// ---------------------------------------------------------------------------
__device__ __half g_wih_h[TH * INP];
__device__ __half g_whh_h[TH * HID];
__device__ __half g_wc_h[2048 * HID];   // Wih[:, :1024] + Whh for gates r,z
__device__ __half g_obs_h[NBUOY * 512];
__device__ __half g_h0[NBUOY * HID];
__device__ __half g_h1[NBUOY * HID];
__device__ __half g_h2[NBUOY * HID];
__device__ __half g_h3[NBUOY * HID];
__device__ float  g_f0[NBUOY * HID];
__device__ float  g_f1[NBUOY * HID];
__device__ float  g_embproj[NEMB * TH];

// ---------------------------------------------------------------------------
// helpers
// ---------------------------------------------------------------------------
__device__ __forceinline__ uint32_t smem_u32(const void* p) {
    uint32_t a;
    asm("{ .reg .u64 t; cvta.to.shared.u64 t, %1; cvt.u32.u64 %0, t; }" : "=r"(a) : "l"(p));
    return a;
}
#define SWZ(b) ((b) ^ (((b) >> 3) & 0x70))

#define CP_ASYNC16(dst, src) \
    asm volatile("cp.async.cg.shared.global [%0], [%1], 16;" :: "r"(dst), "l"(src) : "memory")

__device__ __forceinline__ void ldsm_x4(uint32_t r[4], uint32_t addr) {
    asm volatile("ldmatrix.sync.aligned.m8n8.x4.shared.b16 {%0,%1,%2,%3}, [%4];"
                 : "=r"(r[0]), "=r"(r[1]), "=r"(r[2]), "=r"(r[3]) : "r"(addr));
}

__device__ __forceinline__ void mma16816(float c[4], const uint32_t a[4], const uint32_t b[2]) {
    asm volatile("mma.sync.aligned.m16n8k16.row.col.f32.f16.f16.f32 "
                 "{%0,%1,%2,%3},{%4,%5,%6,%7},{%8,%9},{%0,%1,%2,%3};"
                 : "+f"(c[0]), "+f"(c[1]), "+f"(c[2]), "+f"(c[3])
                 : "r"(a[0]), "r"(a[1]), "r"(a[2]), "r"(a[3]), "r"(b[0]), "r"(b[1]));
}

// ---------------------------------------------------------------------------
// chunk loader: one K-chunk (A 128x64 fp16 + 3 B gate tiles 32x64)
// ---------------------------------------------------------------------------
template <bool GH, bool GI>
__device__ __forceinline__ void load_chunk(
    int c, uint32_t sbase,
    const __half* __restrict__ hA, const __half* __restrict__ giA,
    const __half* __restrict__ obs, int obsWcol,
    const __half* __restrict__ Whh, const __half* __restrict__ Wih,
    int iBase, int jBase, int tid)
{
    constexpr int NCGH = GH ? 16 : 0;
    constexpr int NCGI = GI ? 16 : 0;
    const __half* Ap; int lda, acol; const __half* Bp; int ldb, bcol;
    if (GH && c < NCGH) {
        Ap = hA;  lda = 1024; acol = c * 64;
        Bp = Whh; ldb = 1024; bcol = c * 64;
    } else if (GI && c < NCGH + NCGI) {
        int k = c - NCGH;
        Ap = giA; lda = 1024; acol = k * 64;
        Bp = Wih; ldb = 1088; bcol = k * 64;
    } else {
        Ap = obs; lda = 512;  acol = 0;
        Bp = Wih; ldb = 1088; bcol = obsWcol;
    }
    uint32_t sb = sbase + (c % NSTAGE) * STAGE_BYTES;
    #pragma unroll
    for (int p = 0; p < 4; ++p) {
        int q = tid + (p << 8);
        int row = q >> 3, c8 = q & 7;
        const __half* src = Ap + (size_t)(iBase + row) * lda + acol + c8 * 8;
        CP_ASYNC16(sb + SWZ(row * 128 + c8 * 16), src);
    }
    #pragma unroll
    for (int p = 0; p < 3; ++p) {
        int q = tid + (p << 8);
        int g = q >> 8, rr = (q >> 3) & 31, c8 = q & 7;
        const __half* src = Bp + (size_t)(g * 1024 + jBase + rr) * ldb + bcol + c8 * 8;
        CP_ASYNC16(sb + 16384 + g * 4096 + SWZ(rr * 128 + c8 * 16), src);
    }
    asm volatile("cp.async.commit_group;" ::: "memory");
}

// ---------------------------------------------------------------------------
// Fused GRU step (fp16 mma.sync, 4-stage cp.async pipeline, 2 CTAs/SM)
// ---------------------------------------------------------------------------
template <bool GH, bool GI, bool EMB, bool WR>
__global__ void __launch_bounds__(256, 2) gru_fp16_kernel(
    const __half* __restrict__ hA,
    const __half* __restrict__ giA,
    const __half* __restrict__ obs,   // pre-offset by t*64, lda=512
    int obsWcol,
    const __half* __restrict__ Whh,
    const __half* __restrict__ Wih,
    const float* __restrict__ b_ih,
    const float* __restrict__ b_hh,
    const int* __restrict__ ids,
    const float* __restrict__ hprev,
    float* __restrict__ hout,
    __half* __restrict__ hrnd)
{
    extern __shared__ __align__(1024) unsigned char smem[];
    constexpr int NCGH = GH ? 16 : 0;
    constexpr int NCGI = GI ? 16 : 0;
    constexpr int NC = NCGH + NCGI + 1;

    const int tid  = threadIdx.x;
    const int lane = tid & 31;
    const int warp = tid >> 5;
    const int wm   = warp & 3;
    const int wn   = warp >> 2;
    const int iBase = blockIdx.y * BM;
    const int jBase = blockIdx.x * BNG;
    const uint32_t sbase = smem_u32(smem);

    const int a_row = wm * 32 + ((lane >> 3) & 1) * 8 + (lane & 7);
    const int a_kx  = ((lane >> 4) & 1) * 16;
    const uint32_t a_xor = (uint32_t)((a_row & 7) << 4);
    const int b_row = wn * 16 + ((lane >> 4) & 1) * 8 + (lane & 7);
    const int b_kx  = ((lane >> 3) & 1) * 16;
    const uint32_t b_xor = (uint32_t)((b_row & 7) << 4);

    float aR[2][2][4] = {}, aZ[2][2][4] = {}, aNi[2][2][4] = {}, aNh[2][2][4] = {};

    int loaded = 0;
    #pragma unroll
    for (; loaded < 3 && loaded < NC; ++loaded)
        load_chunk<GH, GI>(loaded, sbase, hA, giA, obs, obsWcol, Whh, Wih, iBase, jBase, tid);

    #pragma unroll 1
    for (int c = 0; c < NC; ++c) {
        if      (loaded == c + 3) asm volatile("cp.async.wait_group 2;" ::: "memory");
        else if (loaded == c + 2) asm volatile("cp.async.wait_group 1;" ::: "memory");
        else                      asm volatile("cp.async.wait_group 0;" ::: "memory");
        __syncthreads();
        if (loaded < NC) {
            load_chunk<GH, GI>(loaded, sbase, hA, giA, obs, obsWcol, Whh, Wih, iBase, jBase, tid);
            ++loaded;
        }
        const bool useNh = GH && (c < NCGH);
        uint32_t sb = sbase + (c % NSTAGE) * STAGE_BYTES;

        #pragma unroll
        for (int k16 = 0; k16 < 4; ++k16) {
            uint32_t a[2][4];
            #pragma unroll
            for (int mt = 0; mt < 2; ++mt)
                ldsm_x4(a[mt], sb + (uint32_t)((a_row + mt * 16) * 128) +
                               ((uint32_t)(k16 * 32 + a_kx) ^ a_xor));
            #pragma unroll
            for (int g = 0; g < 3; ++g) {
                uint32_t r[4];
                ldsm_x4(r, sb + 16384 + g * 4096 + (uint32_t)(b_row * 128) +
                           ((uint32_t)(k16 * 32 + b_kx) ^ b_xor));
                uint32_t bb0[2] = { r[0], r[1] };
                uint32_t bb1[2] = { r[2], r[3] };
                float (*acc)[2][4] = (g == 0) ? aR : (g == 1) ? aZ : (useNh ? aNh : aNi);
                #pragma unroll
                for (int mt = 0; mt < 2; ++mt) {
                    mma16816(acc[mt][0], a[mt], bb0);
                    mma16816(acc[mt][1], a[mt], bb1);
                }
            }
        }
    }

    const int row0 = iBase + wm * 32 + (lane >> 2);
    const int col0 = jBase + wn * 16 + (lane & 3) * 2;
    #pragma unroll
    for (int mt = 0; mt < 2; ++mt) {
        #pragma unroll
        for (int rh = 0; rh < 2; ++rh) {
            const int i = row0 + mt * 16 + rh * 8;
            const float* ep = EMB ? (g_embproj + (size_t)ids[i] * TH) : b_ih;
            #pragma unroll
            for (int nt = 0; nt < 2; ++nt) {
                const int jg = col0 + nt * 8;
                float2 gr  = *(const float2*)&ep[jg];
                float2 gz  = *(const float2*)&ep[jg + 1024];
                float2 gn  = *(const float2*)&ep[jg + 2048];
                float2 bhr = *(const float2*)&b_hh[jg];
                float2 bhz = *(const float2*)&b_hh[jg + 1024];
                float2 bhn = *(const float2*)&b_hh[jg + 2048];
                float2 hp = GH ? *(const float2*)&hprev[(size_t)i * 1024 + jg]
                               : make_float2(0.f, 0.f);
                float2 hv;
                #pragma unroll
                for (int e = 0; e < 2; ++e) {
                    float rp = aR[mt][nt][rh * 2 + e] + (e ? gr.y : gr.x) + (e ? bhr.y : bhr.x);
                    float zp = aZ[mt][nt][rh * 2 + e] + (e ? gz.y : gz.x) + (e ? bhz.y : bhz.x);
                    float ni = aNi[mt][nt][rh * 2 + e] + (e ? gn.y : gn.x);
                    float nh = (GH ? aNh[mt][nt][rh * 2 + e] : 0.f) + (e ? bhn.y : bhn.x);
                    float r = 1.f / (1.f + expf(-rp));
                    float z = 1.f / (1.f + expf(-zp));
                    float n = tanhf(ni + r * nh);
                    float h = (1.f - z) * n + z * (e ? hp.y : hp.x);
                    if (e) hv.y = h; else hv.x = h;
                }
                *(float2*)&hout[(size_t)i * 1024 + jg] = hv;
                if (WR)
                    *(__half2*)&hrnd[(size_t)i * 1024 + jg] = __floats2half2_rn(hv.x, hv.y);
            }
        }
    }
}

// ---------------------------------------------------------------------------
// Step-4 combined kernel: x = [h, obs], hA == giA == h.
// Gates r,z use Wc = Wih[:, :1024]+Whh; gate n keeps Wih_n and Whh_n separate.
// Chunks 0..15: 4 gate tiles vs one A tile; chunk 16: obs (3 gates).
// ---------------------------------------------------------------------------
__device__ __forceinline__ void load_chunk_comb(
    int c, uint32_t sbase,
    const __half* __restrict__ hA,
    const __half* __restrict__ obs, int obsWcol,
    const __half* __restrict__ Wc,
    const __half* __restrict__ Whh, const __half* __restrict__ Wih,
    int iBase, int jBase, int tid)
{
    uint32_t sb = sbase + (c % 3) * STAGE_C;
    const __half* Ap; int lda, acol;
    if (c < 16) { Ap = hA;  lda = 1024; acol = c * 64; }
    else        { Ap = obs; lda = 512;  acol = 0; }

    #pragma unroll
    for (int p = 0; p < 4; ++p) {
        int q = tid + (p << 8);
        int row = q >> 3, c8 = q & 7;
        const __half* src = Ap + (size_t)(iBase + row) * lda + acol + c8 * 8;
        CP_ASYNC16(sb + SWZ(row * 128 + c8 * 16), src);
    }
    if (c < 16) {
        // 4 gates x 32 rows x 128B = 1024 x 16B -> 4 iters
        #pragma unroll
        for (int p = 0; p < 4; ++p) {
            int q = tid + (p << 8);
            int g = q >> 8, rr = (q >> 3) & 31, c8 = q & 7;
            const __half* src;
            if (g < 2)      src = Wc  + (size_t)(g * 1024 + jBase + rr) * 1024 + c * 64 + c8 * 8;
            else if (g == 2) src = Wih + (size_t)(2048 + jBase + rr) * 1088 + c * 64 + c8 * 8;
            else             src = Whh + (size_t)(2048 + jBase + rr) * 1024 + c * 64 + c8 * 8;
            CP_ASYNC16(sb + 16384 + g * 4096 + SWZ(rr * 128 + c8 * 16), src);
        }
    } else {
        #pragma unroll
        for (int p = 0; p < 3; ++p) {
            int q = tid + (p << 8);
            int g = q >> 8, rr = (q >> 3) & 31, c8 = q & 7;
            const __half* src = Wih + (size_t)(g * 1024 + jBase + rr) * 1088 + obsWcol + c8 * 8;
            CP_ASYNC16(sb + 16384 + g * 4096 + SWZ(rr * 128 + c8 * 16), src);
        }
    }
    asm volatile("cp.async.commit_group;" ::: "memory");
}

__global__ void __launch_bounds__(256, 2) gru_comb_kernel(
    const __half* __restrict__ hA,    // rounded h3
    const __half* __restrict__ obs,   // pre-offset, lda=512
    int obsWcol,
    const __half* __restrict__ Wc,
    const __half* __restrict__ Whh,
    const __half* __restrict__ Wih,
    const float* __restrict__ b_ih,
    const float* __restrict__ b_hh,
    const float* __restrict__ hprev,  // fp32 h3
    float* __restrict__ hout)
{
    extern __shared__ __align__(1024) unsigned char smem[];
    constexpr int NC = 17;

    const int tid  = threadIdx.x;
    const int lane = tid & 31;
    const int warp = tid >> 5;
    const int wm   = warp & 3;
    const int wn   = warp >> 2;
    const int iBase = blockIdx.y * BM;
    const int jBase = blockIdx.x * BNG;
    const uint32_t sbase = smem_u32(smem);

    const int a_row = wm * 32 + ((lane >> 3) & 1) * 8 + (lane & 7);
    const int a_kx  = ((lane >> 4) & 1) * 16;
    const uint32_t a_xor = (uint32_t)((a_row & 7) << 4);
    const int b_row = wn * 16 + ((lane >> 4) & 1) * 8 + (lane & 7);
    const int b_kx  = ((lane >> 3) & 1) * 16;
    const uint32_t b_xor = (uint32_t)((b_row & 7) << 4);

    float aR[2][2][4] = {}, aZ[2][2][4] = {}, aNi[2][2][4] = {}, aNh[2][2][4] = {};

    int loaded = 0;
    #pragma unroll
    for (; loaded < 2; ++loaded)
        load_chunk_comb(loaded, sbase, hA, obs, obsWcol, Wc, Whh, Wih, iBase, jBase, tid);

    #pragma unroll 1
    for (int c = 0; c < NC; ++c) {
        if (loaded == c + 2) asm volatile("cp.async.wait_group 1;" ::: "memory");
        else                 asm volatile("cp.async.wait_group 0;" ::: "memory");
        __syncthreads();
        if (loaded < NC) {
            load_chunk_comb(loaded, sbase, hA, obs, obsWcol, Wc, Whh, Wih, iBase, jBase, tid);
            ++loaded;
        }
        const int ng = (c < 16) ? 4 : 3;
        uint32_t sb = sbase + (c % 3) * STAGE_C;

        #pragma unroll
        for (int k16 = 0; k16 < 4; ++k16) {
            uint32_t a[2][4];
            #pragma unroll
            for (int mt = 0; mt < 2; ++mt)
                ldsm_x4(a[mt], sb + (uint32_t)((a_row + mt * 16) * 128) +
                               ((uint32_t)(k16 * 32 + a_kx) ^ a_xor));
            #pragma unroll
            for (int g = 0; g < 4; ++g) {
                if (g >= ng) break;
                uint32_t r[4];
                ldsm_x4(r, sb + 16384 + g * 4096 + (uint32_t)(b_row * 128) +
                           ((uint32_t)(k16 * 32 + b_kx) ^ b_xor));
                uint32_t bb0[2] = { r[0], r[1] };
                uint32_t bb1[2] = { r[2], r[3] };
                float (*acc)[2][4] = (g == 0) ? aR : (g == 1) ? aZ : (g == 2) ? aNi : aNh;
                #pragma unroll
                for (int mt = 0; mt < 2; ++mt) {
                    mma16816(acc[mt][0], a[mt], bb0);
                    mma16816(acc[mt][1], a[mt], bb1);
                }
            }
        }
    }

    const int row0 = iBase + wm * 32 + (lane >> 2);
    const int col0 = jBase + wn * 16 + (lane & 3) * 2;
    #pragma unroll
    for (int mt = 0; mt < 2; ++mt) {
        #pragma unroll
        for (int rh = 0; rh < 2; ++rh) {
            const int i = row0 + mt * 16 + rh * 8;
            #pragma unroll
            for (int nt = 0; nt < 2; ++nt) {
                const int jg = col0 + nt * 8;
                float2 gr  = *(const float2*)&b_ih[jg];
                float2 gz  = *(const float2*)&b_ih[jg + 1024];
                float2 gn  = *(const float2*)&b_ih[jg + 2048];
                float2 bhr = *(const float2*)&b_hh[jg];
                float2 bhz = *(const float2*)&b_hh[jg + 1024];
                float2 bhn = *(const float2*)&b_hh[jg + 2048];
                float2 hp  = *(const float2*)&hprev[(size_t)i * 1024 + jg];
                float2 hv;
                #pragma unroll
                for (int e = 0; e < 2; ++e) {
                    float rp = aR[mt][nt][rh * 2 + e] + (e ? gr.y : gr.x) + (e ? bhr.y : bhr.x);
                    float zp = aZ[mt][nt][rh * 2 + e] + (e ? gz.y : gz.x) + (e ? bhz.y : bhz.x);
                    float ni = aNi[mt][nt][rh * 2 + e] + (e ? gn.y : gn.x);
                    float nh = aNh[mt][nt][rh * 2 + e] + (e ? bhn.y : bhn.x);
                    float r = 1.f / (1.f + expf(-rp));
                    float z = 1.f / (1.f + expf(-zp));
                    float n = tanhf(ni + r * nh);
                    float h = (1.f - z) * n + z * (e ? hp.y : hp.x);
                    if (e) hv.y = h; else hv.x = h;
                }
                *(float2*)&hout[(size_t)i * 1024 + jg] = hv;
            }
        }
    }
}

// ---------------------------------------------------------------------------
// Prep kernels
// ---------------------------------------------------------------------------
__global__ void __launch_bounds__(256) f2h_kernel(
    const float4* __restrict__ src, __half2* __restrict__ dst, int n4)
{
    int i = blockIdx.x * 256 + threadIdx.x;
    if (i < n4) {
        float4 v = src[i];
        dst[i * 2 + 0] = __floats2half2_rn(v.x, v.y);
        dst[i * 2 + 1] = __floats2half2_rn(v.z, v.w);
    }
}

// g_wc_h[j*1024+k] = half(Wih[j*1088+k] + Whh[j*1024+k]),  j in [0, 2048)
__global__ void __launch_bounds__(256) wsum_kernel(
    const float* __restrict__ Wih, const float* __restrict__ Whh)
{
    int idx = blockIdx.x * 256 + threadIdx.x;   // one float4 (4 elems) each
    int j  = idx >> 8;
    int kc = (idx & 255) * 4;
    float4 a = *(const float4*)&Wih[(size_t)j * 1088 + kc];
    float4 b = *(const float4*)&Whh[(size_t)j * 1024 + kc];
    __half2* d = (__half2*)&g_wc_h[(size_t)j * 1024 + kc];
    d[0] = __floats2half2_rn(a.x + b.x, a.y + b.y);
    d[1] = __floats2half2_rn(a.z + b.z, a.w + b.w);
}

__global__ void __launch_bounds__(128) embproj_kernel(
    const float* __restrict__ emb,
    const float* __restrict__ Wih,
    const float* __restrict__ b_ih)
{
    __shared__ float se[10][1024];
    const int tid = threadIdx.x;
    const int eg = blockIdx.y;
    const int j = blockIdx.x * 128 + tid;

    for (int q = tid; q < 10 * 256; q += 128) {
        int e = q >> 8;
        int k = (q & 255) * 4;
        float4 v = *(const float4*)&emb[(size_t)(eg * 10 + e) * 1024 + k];
        se[e][k] = v.x; se[e][k + 1] = v.y; se[e][k + 2] = v.z; se[e][k + 3] = v.w;
    }
    __syncthreads();

    float acc[10];
    #pragma unroll
    for (int e = 0; e < 10; ++e) acc[e] = 0.f;
    const float* w = Wih + (size_t)j * INP + 64;
    for (int k = 0; k < 1024; k += 4) {
        float4 wv = *(const float4*)&w[k];
        #pragma unroll
        for (int e = 0; e < 10; ++e)
            acc[e] += wv.x * se[e][k] + wv.y * se[e][k + 1] +
                      wv.z * se[e][k + 2] + wv.w * se[e][k + 3];
    }
    float b = b_ih[j];
    #pragma unroll
    for (int e = 0; e < 10; ++e)
        g_embproj[(size_t)(eg * 10 + e) * TH + j] = b + acc[e];
}

// ---------------------------------------------------------------------------
extern "C" void kernel_launch(void* const* d_in, const int* in_sizes, int n_in,
                              void* d_out, int out_size)
{
    const float* obs  = (const float*)d_in[0];
    const int*   ids  = (const int*)  d_in[1];
    const float* emb  = (const float*)d_in[2];
    const float* Wih  = (const float*)d_in[3];
    const float* Whh  = (const float*)d_in[4];
    const float* b_ih = (const float*)d_in[5];
    const float* b_hh = (const float*)d_in[6];
    float* out = (float*)d_out;

    void *pwi, *pwh, *pwc, *pob, *ph0, *ph1, *ph2, *ph3, *pf0, *pf1;
    cudaGetSymbolAddress(&pwi, g_wih_h);
    cudaGetSymbolAddress(&pwh, g_whh_h);
    cudaGetSymbolAddress(&pwc, g_wc_h);
    cudaGetSymbolAddress(&pob, g_obs_h);
    cudaGetSymbolAddress(&ph0, g_h0);
    cudaGetSymbolAddress(&ph1, g_h1);
    cudaGetSymbolAddress(&ph2, g_h2);
    cudaGetSymbolAddress(&ph3, g_h3);
    cudaGetSymbolAddress(&pf0, g_f0);
    cudaGetSymbolAddress(&pf1, g_f1);
    __half *wih_h = (__half*)pwi, *whh_h = (__half*)pwh, *wc_h = (__half*)pwc, *obs_h = (__half*)pob;
    __half *h0 = (__half*)ph0, *h1 = (__half*)ph1, *h2 = (__half*)ph2, *h3 = (__half*)ph3;
    float *f0 = (float*)pf0, *f1 = (float*)pf1;

    cudaFuncSetAttribute(gru_fp16_kernel<false, false, true,  true >, cudaFuncAttributeMaxDynamicSharedMemorySize, SMEM_BYTES);
    cudaFuncSetAttribute(gru_fp16_kernel<true,  false, true,  true >, cudaFuncAttributeMaxDynamicSharedMemorySize, SMEM_BYTES);
    cudaFuncSetAttribute(gru_fp16_kernel<true,  true,  false, true >, cudaFuncAttributeMaxDynamicSharedMemorySize, SMEM_BYTES);
    cudaFuncSetAttribute(gru_comb_kernel, cudaFuncAttributeMaxDynamicSharedMemorySize, SMEM_C);

    // Prep
    f2h_kernel<<<(TH * INP / 4 + 255) / 256, 256>>>((const float4*)Wih, (__half2*)wih_h, TH * INP / 4);
    f2h_kernel<<<(TH * HID / 4 + 255) / 256, 256>>>((const float4*)Whh, (__half2*)whh_h, TH * HID / 4);
    f2h_kernel<<<(NBUOY * 512 / 4 + 255) / 256, 256>>>((const float4*)obs, (__half2*)obs_h, NBUOY * 512 / 4);
    wsum_kernel<<<2048 * 256 / 256, 256>>>(Wih, Whh);
    embproj_kernel<<<dim3(TH / 128, 10), 128>>>(emb, Wih, b_ih);

    dim3 gs(HID / BNG, NBUOY / BM);  // (32, 128)

    // step 0: h=0; gi = obs0 @ Wih[:, :64]^T + embproj[id]
    gru_fp16_kernel<false, false, true, true><<<gs, 256, SMEM_BYTES>>>(
        nullptr, nullptr, obs_h + 0, 0, whh_h, wih_h, b_ih, b_hh, ids, nullptr, f0, h0);
    // step 1
    gru_fp16_kernel<true, false, true, true><<<gs, 256, SMEM_BYTES>>>(
        h0, nullptr, obs_h + 64, 0, whh_h, wih_h, b_ih, b_hh, ids, f0, f1, h1);
    // step 2
    gru_fp16_kernel<true, false, true, true><<<gs, 256, SMEM_BYTES>>>(
        h1, nullptr, obs_h + 128, 0, whh_h, wih_h, b_ih, b_hh, ids, f1, f0, h2);
    // step 3: x = [h0, obs1]
    gru_fp16_kernel<true, true, false, true><<<gs, 256, SMEM_BYTES>>>(
        h2, h0, obs_h + 64, 1024, whh_h, wih_h, b_ih, b_hh, ids, f0, f1, h3);
    // step 4 (combined weights): x = [h3, obs2] -> final output
    gru_comb_kernel<<<gs, 256, SMEM_C>>>(
        h3, obs_h + 128, 1024, wc_h, whh_h, wih_h, b_ih, b_hh, f1, out);
}